// round 3
// baseline (speedup 1.0000x reference)
#include <cuda_runtime.h>
#include <cstdint>

#define NNODE 10000
#define BNUM  4
#define DDIM  128
#define ECAP  262144
#define ND    (NNODE*DDIM)
#define SLOPE 0.01f

// ---------------- scratch (device globals; no allocation) ----------------
__device__ float g_x[BNUM*ND];      // layer activations (output of each layer)
__device__ float g_h[BNUM*ND];      // per-layer hidden h
__device__ float g_asrc[BNUM*NNODE];
__device__ float g_adst[BNUM*NNODE];
__device__ int   g_offs[NNODE+1];
__device__ int   g_cur[NNODE];      // counts -> cursor
__device__ int   g_srcs[ECAP];
__device__ float g_wnsW[3*DDIM];
__device__ float g_bnsW[3*DDIM];
__device__ float g_semb[BNUM*DDIM];
__device__ float g_rs[BNUM];

// ---------------- f32x2 helpers ----------------
__device__ __forceinline__ unsigned long long pack2(float x, float y) {
    unsigned long long r;
    asm("mov.b64 %0, {%1, %2};" : "=l"(r) : "f"(x), "f"(y));
    return r;
}
__device__ __forceinline__ unsigned long long ffma2(unsigned long long a,
                                                    unsigned long long b,
                                                    unsigned long long c) {
    unsigned long long d;
    asm("fma.rn.f32x2 %0, %1, %2, %3;" : "=l"(d) : "l"(a), "l"(b), "l"(c));
    return d;
}
__device__ __forceinline__ float2 unpack2(unsigned long long v) {
    float2 f;
    asm("mov.b64 {%0, %1}, %2;" : "=f"(f.x), "=f"(f.y) : "l"(v));
    return f;
}

// ---------------- CSR build ----------------
__global__ void k_zero_cnt() {
    int i = blockIdx.x*blockDim.x + threadIdx.x;
    if (i < NNODE) g_cur[i] = 0;
}
__global__ void k_hist(const int* __restrict__ ei, int Etot) {
    int e = blockIdx.x*blockDim.x + threadIdx.x;
    if (e < Etot) atomicAdd(&g_cur[ei[Etot + e]], 1);
}
__global__ void k_scan(int Etot) {
    __shared__ int sh[1024];
    const int ITEMS = 10;   // ceil(10000/1024)
    int t = threadIdx.x;
    int base = t*ITEMS;
    int loc[ITEMS]; int sum = 0;
#pragma unroll
    for (int i = 0; i < ITEMS; i++) {
        int idx = base + i;
        int v = (idx < NNODE) ? g_cur[idx] : 0;
        loc[i] = sum; sum += v;
    }
    sh[t] = sum; __syncthreads();
    for (int off = 1; off < 1024; off <<= 1) {
        int v = (t >= off) ? sh[t-off] : 0;
        __syncthreads();
        sh[t] += v;
        __syncthreads();
    }
    int pre = t ? sh[t-1] : 0;
#pragma unroll
    for (int i = 0; i < ITEMS; i++) {
        int idx = base + i;
        if (idx < NNODE) { int o = pre + loc[i]; g_offs[idx] = o; g_cur[idx] = o; }
    }
    if (t == 1023) g_offs[NNODE] = sh[1023];
}
__global__ void k_scatter(const int* __restrict__ ei, int Etot) {
    int e = blockIdx.x*blockDim.x + threadIdx.x;
    if (e < Etot) {
        int d = ei[Etot + e];
        int pos = atomicAdd(&g_cur[d], 1);
        g_srcs[pos] = ei[e];
    }
}

// ---------------- precompute WnsW / bnsW ----------------
__global__ void k_prep(const float* __restrict__ W, const float* __restrict__ Wns,
                       const float* __restrict__ bns) {
    int l = blockIdx.x, c = threadIdx.x;
    const float* Wl = W + l*DDIM*DDIM;
    float aw = 0.f, ab = 0.f;
    for (int k = 0; k < DDIM; k++) {
        float w = Wl[k*DDIM + c];
        aw += Wns[l*DDIM + k]*w;
        ab += bns[l*DDIM + k]*w;
    }
    g_wnsW[l*DDIM + c] = aw;
    g_bnsW[l*DDIM + c] = ab;
}

// ---------------- fused GEMM (64x128 tile, f32x2) ----------------
// MODE 0: h = x@W (+ state*WnsW + bnsW), plus a_src/a_dst epilogue
// MODE 1: out[b,n] = rs[b] + sum_d relu((x@W2)[d]+b2[d])*W3[128+d]
#define XST 76  // padded stride: conflict-free transposed stores & aligned f4 reads
template<int MODE>
__global__ void k_gemm(const float* __restrict__ xext, long bstride,
                       const float* __restrict__ W,
                       const float* __restrict__ state,
                       const float* __restrict__ attS, const float* __restrict__ attD,
                       int layer,
                       const float* __restrict__ b2, const float* __restrict__ W3,
                       float* __restrict__ out) {
    __shared__ float xsT[32][XST];
    __shared__ float ws[32][DDIM];
    const int tid = threadIdx.x;
    const int tx = tid & 31, ty = tid >> 5;
    const int b = blockIdx.y;
    const int rowbase = blockIdx.x * 64;
    const float* xp = xext ? xext : g_x;
    const size_t xboff = (size_t)b * (size_t)bstride;

    unsigned long long acc[4][4];
#pragma unroll
    for (int rp = 0; rp < 4; rp++)
#pragma unroll
        for (int c = 0; c < 4; c++) acc[rp][c] = 0ull;

    for (int kc = 0; kc < 4; ++kc) {
#pragma unroll
        for (int v = tid; v < 512; v += 256) {
            int r = v >> 3, kq = v & 7;
            int rowc = rowbase + r; rowc = rowc < NNODE ? rowc : NNODE-1;
            const float4 xv = *(const float4*)(xp + xboff + (size_t)rowc*DDIM + kc*32 + kq*4);
            int k0 = kq*4;
            xsT[k0+0][r] = xv.x; xsT[k0+1][r] = xv.y;
            xsT[k0+2][r] = xv.z; xsT[k0+3][r] = xv.w;
        }
#pragma unroll
        for (int v = tid; v < 1024; v += 256) {
            int kk = v >> 5, cq = v & 31;
            *(float4*)&ws[kk][cq*4] = *(const float4*)(W + (size_t)(kc*32+kk)*DDIM + cq*4);
        }
        __syncthreads();
#pragma unroll
        for (int kk = 0; kk < 32; ++kk) {
            float4 wv = *(const float4*)&ws[kk][tx*4];
            float4 a0 = *(const float4*)&xsT[kk][ty*8];
            float4 a1 = *(const float4*)&xsT[kk][ty*8+4];
            unsigned long long ar[4] = {pack2(a0.x,a0.y), pack2(a0.z,a0.w),
                                        pack2(a1.x,a1.y), pack2(a1.z,a1.w)};
            unsigned long long wd[4] = {pack2(wv.x,wv.x), pack2(wv.y,wv.y),
                                        pack2(wv.z,wv.z), pack2(wv.w,wv.w)};
#pragma unroll
            for (int rp = 0; rp < 4; rp++)
#pragma unroll
                for (int c = 0; c < 4; c++)
                    acc[rp][c] = ffma2(ar[rp], wd[c], acc[rp][c]);
        }
        __syncthreads();
    }

    float2 A[4][4];
#pragma unroll
    for (int rp = 0; rp < 4; rp++)
#pragma unroll
        for (int c = 0; c < 4; c++) A[rp][c] = unpack2(acc[rp][c]);

    const int r0 = rowbase + ty*8;
    const int lane = tx;

    if (MODE == 0) {
        float st[8];
#pragma unroll
        for (int i = 0; i < 8; i++) {
            int rr = r0 + i; rr = rr < NNODE ? rr : NNODE-1;
            st[i] = state[(size_t)b*NNODE + rr];
        }
        float4 wn = *(const float4*)(g_wnsW + layer*DDIM + tx*4);
        float4 bn = *(const float4*)(g_bnsW + layer*DDIM + tx*4);
        float wnc[4] = {wn.x, wn.y, wn.z, wn.w};
        float bnc[4] = {bn.x, bn.y, bn.z, bn.w};
#pragma unroll
        for (int rp = 0; rp < 4; rp++)
#pragma unroll
            for (int c = 0; c < 4; c++) {
                A[rp][c].x += st[2*rp]   * wnc[c] + bnc[c];
                A[rp][c].y += st[2*rp+1] * wnc[c] + bnc[c];
            }
        float4 as4 = *(const float4*)(attS + tx*4);
        float4 ad4 = *(const float4*)(attD + tx*4);
        float asc[4] = {as4.x, as4.y, as4.z, as4.w};
        float adc[4] = {ad4.x, ad4.y, ad4.z, ad4.w};
        float asr[8], ads[8];
#pragma unroll
        for (int i = 0; i < 8; i++) { asr[i] = 0.f; ads[i] = 0.f; }
#pragma unroll
        for (int rp = 0; rp < 4; rp++)
#pragma unroll
            for (int c = 0; c < 4; c++) {
                asr[2*rp]   += A[rp][c].x * asc[c];
                asr[2*rp+1] += A[rp][c].y * asc[c];
                ads[2*rp]   += A[rp][c].x * adc[c];
                ads[2*rp+1] += A[rp][c].y * adc[c];
            }
#pragma unroll
        for (int off = 16; off > 0; off >>= 1)
#pragma unroll
            for (int i = 0; i < 8; i++) {
                asr[i] += __shfl_xor_sync(0xffffffffu, asr[i], off);
                ads[i] += __shfl_xor_sync(0xffffffffu, ads[i], off);
            }
        if (lane == 0) {
#pragma unroll
            for (int i = 0; i < 8; i++) {
                int row = r0 + i;
                if (row < NNODE) {
                    g_asrc[(size_t)b*NNODE + row] = asr[i];
                    g_adst[(size_t)b*NNODE + row] = ads[i];
                }
            }
        }
        float* hb = g_h + (size_t)b*ND;
#pragma unroll
        for (int rp = 0; rp < 4; rp++) {
            int re = r0 + 2*rp, ro = re + 1;
            float4 ve = {A[rp][0].x, A[rp][1].x, A[rp][2].x, A[rp][3].x};
            float4 vo = {A[rp][0].y, A[rp][1].y, A[rp][2].y, A[rp][3].y};
            if (re < NNODE) *(float4*)(hb + (size_t)re*DDIM + tx*4) = ve;
            if (ro < NNODE) *(float4*)(hb + (size_t)ro*DDIM + tx*4) = vo;
        }
    } else {
        float4 b2v = *(const float4*)(b2 + tx*4);
        float4 w3v = *(const float4*)(W3 + DDIM + tx*4);
        float b2c[4] = {b2v.x, b2v.y, b2v.z, b2v.w};
        float w3c[4] = {w3v.x, w3v.y, w3v.z, w3v.w};
        float ra[8];
#pragma unroll
        for (int i = 0; i < 8; i++) ra[i] = 0.f;
#pragma unroll
        for (int rp = 0; rp < 4; rp++)
#pragma unroll
            for (int c = 0; c < 4; c++) {
                float vx = fmaxf(A[rp][c].x + b2c[c], 0.f);
                float vy = fmaxf(A[rp][c].y + b2c[c], 0.f);
                ra[2*rp]   += vx * w3c[c];
                ra[2*rp+1] += vy * w3c[c];
            }
#pragma unroll
        for (int off = 16; off > 0; off >>= 1)
#pragma unroll
            for (int i = 0; i < 8; i++)
                ra[i] += __shfl_xor_sync(0xffffffffu, ra[i], off);
        if (lane == 0) {
            float rsb = g_rs[b];
#pragma unroll
            for (int i = 0; i < 8; i++) {
                int row = r0 + i;
                if (row < NNODE) out[(size_t)b*NNODE + row] = rsb + ra[i];
            }
        }
    }
}

// ---------------- edge softmax + aggregate (one warp per (dst,b)) ----------------
__global__ void k_edge(const float* __restrict__ bias) {
    int gw = (blockIdx.x*blockDim.x + threadIdx.x) >> 5;
    int lane = threadIdx.x & 31;
    if (gw >= NNODE*BNUM) return;
    int n = gw % NNODE;
    int b = gw / NNODE;
    int e0 = g_offs[n], e1 = g_offs[n+1];
    float adst = g_adst[(size_t)b*NNODE + n];
    const float* asr = g_asrc + (size_t)b*NNODE;
    const float4* hb = (const float4*)(g_h + (size_t)b*ND);
    float4 acc = {0.f, 0.f, 0.f, 0.f};
    float m = -1e30f, s = 0.f;
    for (int e = e0; e < e1; ++e) {
        int sv = g_srcs[e];
        float ae = asr[sv] + adst;
        ae = ae > 0.f ? ae : SLOPE*ae;
        float mn = fmaxf(m, ae);
        float corr = __expf(m - mn);
        float p = __expf(ae - mn);
        s = s*corr + p;
        float4 hv = hb[(size_t)sv*32 + lane];
        acc.x = acc.x*corr + p*hv.x;
        acc.y = acc.y*corr + p*hv.y;
        acc.z = acc.z*corr + p*hv.z;
        acc.w = acc.w*corr + p*hv.w;
        m = mn;
    }
    float inv = 1.f/s;
    float4 bi = ((const float4*)bias)[lane];
    float4 o;
    o.x = fmaxf(acc.x*inv + bi.x, 0.f);
    o.y = fmaxf(acc.y*inv + bi.y, 0.f);
    o.z = fmaxf(acc.z*inv + bi.z, 0.f);
    o.w = fmaxf(acc.w*inv + bi.w, 0.f);
    ((float4*)(g_x + (size_t)b*ND))[(size_t)n*32 + lane] = o;
}

// ---------------- final head ----------------
__global__ void k_zero_semb() { g_semb[threadIdx.x] = 0.f; }

__global__ void k_reduce() {
    int b = blockIdx.y;
    int r0 = blockIdx.x * 250;
    int r1 = r0 + 250; if (r1 > NNODE) r1 = NNODE;
    int col = threadIdx.x & 127;
    int half = threadIdx.x >> 7;
    float acc = 0.f;
    const float* xb = g_x + (size_t)b*ND;
    for (int r = r0 + half; r < r1; r += 2) acc += xb[(size_t)r*DDIM + col];
    __shared__ float sh[256];
    sh[threadIdx.x] = acc; __syncthreads();
    if (half == 0) atomicAdd(&g_semb[b*DDIM + col], sh[col] + sh[col+128]);
}

__global__ void k_beta(const float* __restrict__ W1, const float* __restrict__ b1,
                       const float* __restrict__ W3, const float* __restrict__ b3) {
    int b = blockIdx.x, d = threadIdx.x;
    float acc = b1[d];
    for (int k = 0; k < DDIM; k++) acc += g_semb[b*DDIM + k] * W1[k*DDIM + d];
    float v = fmaxf(acc, 0.f) * W3[d];
    __shared__ float sh[DDIM];
    sh[d] = v; __syncthreads();
    for (int off = 64; off > 0; off >>= 1) {
        if (d < off) sh[d] += sh[d+off];
        __syncthreads();
    }
    if (d == 0) g_rs[b] = sh[0] + b3[0];
}

// ---------------- launch ----------------
extern "C" void kernel_launch(void* const* d_in, const int* in_sizes, int n_in,
                              void* d_out, int out_size) {
    const float* state = (const float*)d_in[0];
    const float* struc = (const float*)d_in[1];
    const int*   ei    = (const int*)d_in[2];
    const float* gatW  = (const float*)d_in[3];
    const float* attS  = (const float*)d_in[4];
    const float* attD  = (const float*)d_in[5];
    const float* Wns   = (const float*)d_in[6];
    const float* bns   = (const float*)d_in[7];
    const float* bias  = (const float*)d_in[8];
    const float* W1    = (const float*)d_in[9];
    const float* b1    = (const float*)d_in[10];
    const float* W2    = (const float*)d_in[11];
    const float* b2    = (const float*)d_in[12];
    const float* W3    = (const float*)d_in[13];
    const float* b3    = (const float*)d_in[14];
    float* out = (float*)d_out;
    int Etot = in_sizes[2] / 2;

    // CSR build (counting sort by dst)
    k_zero_cnt<<<(NNODE+255)/256, 256>>>();
    k_hist<<<(Etot+255)/256, 256>>>(ei, Etot);
    k_scan<<<1, 1024>>>(Etot);
    k_scatter<<<(Etot+255)/256, 256>>>(ei, Etot);
    k_prep<<<3, 128>>>(gatW, Wns, bns);

    dim3 ggrid((NNODE + 63)/64, BNUM);
    for (int l = 0; l < 3; l++) {
        const float* xe = (l == 0) ? struc : nullptr;
        long bs = (l == 0) ? 0L : (long)ND;
        k_gemm<0><<<ggrid, 256>>>(xe, bs, gatW + (size_t)l*DDIM*DDIM, state,
                                  attS + l*DDIM, attD + l*DDIM, l,
                                  nullptr, nullptr, nullptr);
        k_edge<<<(NNODE*BNUM*32)/256, 256>>>(bias + l*DDIM);
    }

    k_zero_semb<<<1, 512>>>();
    k_reduce<<<dim3(40, BNUM), 256>>>();
    k_beta<<<BNUM, 128>>>(W1, b1, W3, b3);
    k_gemm<1><<<ggrid, 256>>>(nullptr, (long)ND, W2, state,
                              nullptr, nullptr, 0, b2, W3, out);
}

// round 4
// speedup vs baseline: 1.0875x; 1.0875x over previous
#include <cuda_runtime.h>
#include <cuda_fp16.h>
#include <cstdint>

#define NNODE 10000
#define BNUM  4
#define DDIM  128
#define ECAP  262144
#define ND    (NNODE*DDIM)
#define SLOPE 0.01f
#define RPARTS 40

// ---------------- scratch (device globals; no allocation) ----------------
__device__ float  g_x[BNUM*ND];      // layer activations (fp32)
__device__ __half g_h[BNUM*ND];      // per-layer hidden h (fp16 payload)
__device__ float g_asrc[BNUM*NNODE];
__device__ float g_adst[BNUM*NNODE];
__device__ int   g_offs[NNODE+1];
__device__ int   g_cur[NNODE];
__device__ int   g_srcs[ECAP];
__device__ float g_wnsW[3*DDIM];
__device__ float g_bnsW[3*DDIM];
__device__ float g_sembp[RPARTS*BNUM*DDIM];
__device__ float g_rs[BNUM];

// ---------------- f32x2 helpers ----------------
__device__ __forceinline__ unsigned long long pack2(float x, float y) {
    unsigned long long r;
    asm("mov.b64 %0, {%1, %2};" : "=l"(r) : "f"(x), "f"(y));
    return r;
}
__device__ __forceinline__ unsigned long long ffma2(unsigned long long a,
                                                    unsigned long long b,
                                                    unsigned long long c) {
    unsigned long long d;
    asm("fma.rn.f32x2 %0, %1, %2, %3;" : "=l"(d) : "l"(a), "l"(b), "l"(c));
    return d;
}
__device__ __forceinline__ float2 unpack2(unsigned long long v) {
    float2 f;
    asm("mov.b64 {%0, %1}, %2;" : "=f"(f.x), "=f"(f.y) : "l"(v));
    return f;
}

// ---------------- init: fused count-zero + WnsW/bnsW precompute ----------------
__global__ void k_init(const float* __restrict__ W, const float* __restrict__ Wns,
                       const float* __restrict__ bns) {
    if (blockIdx.x < 3) {
        int l = blockIdx.x, c = threadIdx.x;
        if (c < DDIM) {
            const float* Wl = W + l*DDIM*DDIM;
            float aw = 0.f, ab = 0.f;
            for (int k = 0; k < DDIM; k++) {
                float w = Wl[k*DDIM + c];
                aw += Wns[l*DDIM + k]*w;
                ab += bns[l*DDIM + k]*w;
            }
            g_wnsW[l*DDIM + c] = aw;
            g_bnsW[l*DDIM + c] = ab;
        }
    } else {
        int i = (blockIdx.x - 3)*256 + threadIdx.x;
        if (i < NNODE) g_cur[i] = 0;
    }
}

// ---------------- CSR build ----------------
__global__ void k_hist(const int* __restrict__ ei, int Etot) {
    int e = blockIdx.x*blockDim.x + threadIdx.x;
    if (e < Etot) atomicAdd(&g_cur[ei[Etot + e]], 1);
}
__global__ void k_scan(int Etot) {
    __shared__ int sh[1024];
    const int ITEMS = 10;
    int t = threadIdx.x;
    int base = t*ITEMS;
    int loc[ITEMS]; int sum = 0;
#pragma unroll
    for (int i = 0; i < ITEMS; i++) {
        int idx = base + i;
        int v = (idx < NNODE) ? g_cur[idx] : 0;
        loc[i] = sum; sum += v;
    }
    sh[t] = sum; __syncthreads();
    for (int off = 1; off < 1024; off <<= 1) {
        int v = (t >= off) ? sh[t-off] : 0;
        __syncthreads();
        sh[t] += v;
        __syncthreads();
    }
    int pre = t ? sh[t-1] : 0;
#pragma unroll
    for (int i = 0; i < ITEMS; i++) {
        int idx = base + i;
        if (idx < NNODE) { int o = pre + loc[i]; g_offs[idx] = o; g_cur[idx] = o; }
    }
    if (t == 1023) g_offs[NNODE] = sh[1023];
}
__global__ void k_scatter(const int* __restrict__ ei, int Etot) {
    int e = blockIdx.x*blockDim.x + threadIdx.x;
    if (e < Etot) {
        int d = ei[Etot + e];
        int pos = atomicAdd(&g_cur[d], 1);
        g_srcs[pos] = ei[e];
    }
}

// ---------------- fused GEMM (64x128 tile, f32x2) ----------------
#define XST 76
template<int MODE>
__global__ void k_gemm(const float* __restrict__ xext, long bstride,
                       const float* __restrict__ W,
                       const float* __restrict__ state,
                       const float* __restrict__ attS, const float* __restrict__ attD,
                       int layer,
                       const float* __restrict__ b2, const float* __restrict__ W3,
                       float* __restrict__ out) {
    __shared__ float xsT[32][XST];
    __shared__ float ws[32][DDIM];
    const int tid = threadIdx.x;
    const int tx = tid & 31, ty = tid >> 5;
    const int b = blockIdx.y;
    const int rowbase = blockIdx.x * 64;
    const float* xp = xext ? xext : g_x;
    const size_t xboff = (size_t)b * (size_t)bstride;

    unsigned long long acc[4][4];
#pragma unroll
    for (int rp = 0; rp < 4; rp++)
#pragma unroll
        for (int c = 0; c < 4; c++) acc[rp][c] = 0ull;

    for (int kc = 0; kc < 4; ++kc) {
#pragma unroll
        for (int v = tid; v < 512; v += 256) {
            int r = v >> 3, kq = v & 7;
            int rowc = rowbase + r; rowc = rowc < NNODE ? rowc : NNODE-1;
            const float4 xv = *(const float4*)(xp + xboff + (size_t)rowc*DDIM + kc*32 + kq*4);
            int k0 = kq*4;
            xsT[k0+0][r] = xv.x; xsT[k0+1][r] = xv.y;
            xsT[k0+2][r] = xv.z; xsT[k0+3][r] = xv.w;
        }
#pragma unroll
        for (int v = tid; v < 1024; v += 256) {
            int kk = v >> 5, cq = v & 31;
            *(float4*)&ws[kk][cq*4] = *(const float4*)(W + (size_t)(kc*32+kk)*DDIM + cq*4);
        }
        __syncthreads();
#pragma unroll
        for (int kk = 0; kk < 32; ++kk) {
            float4 wv = *(const float4*)&ws[kk][tx*4];
            float4 a0 = *(const float4*)&xsT[kk][ty*8];
            float4 a1 = *(const float4*)&xsT[kk][ty*8+4];
            unsigned long long ar[4] = {pack2(a0.x,a0.y), pack2(a0.z,a0.w),
                                        pack2(a1.x,a1.y), pack2(a1.z,a1.w)};
            unsigned long long wd[4] = {pack2(wv.x,wv.x), pack2(wv.y,wv.y),
                                        pack2(wv.z,wv.z), pack2(wv.w,wv.w)};
#pragma unroll
            for (int rp = 0; rp < 4; rp++)
#pragma unroll
                for (int c = 0; c < 4; c++)
                    acc[rp][c] = ffma2(ar[rp], wd[c], acc[rp][c]);
        }
        __syncthreads();
    }

    float2 A[4][4];
#pragma unroll
    for (int rp = 0; rp < 4; rp++)
#pragma unroll
        for (int c = 0; c < 4; c++) A[rp][c] = unpack2(acc[rp][c]);

    const int r0 = rowbase + ty*8;
    const int lane = tx;

    if (MODE == 0) {
        float st[8];
#pragma unroll
        for (int i = 0; i < 8; i++) {
            int rr = r0 + i; rr = rr < NNODE ? rr : NNODE-1;
            st[i] = state[(size_t)b*NNODE + rr];
        }
        float4 wn = *(const float4*)(g_wnsW + layer*DDIM + tx*4);
        float4 bn = *(const float4*)(g_bnsW + layer*DDIM + tx*4);
        float wnc[4] = {wn.x, wn.y, wn.z, wn.w};
        float bnc[4] = {bn.x, bn.y, bn.z, bn.w};
#pragma unroll
        for (int rp = 0; rp < 4; rp++)
#pragma unroll
            for (int c = 0; c < 4; c++) {
                A[rp][c].x += st[2*rp]   * wnc[c] + bnc[c];
                A[rp][c].y += st[2*rp+1] * wnc[c] + bnc[c];
            }
        float4 as4 = *(const float4*)(attS + tx*4);
        float4 ad4 = *(const float4*)(attD + tx*4);
        float asc[4] = {as4.x, as4.y, as4.z, as4.w};
        float adc[4] = {ad4.x, ad4.y, ad4.z, ad4.w};
        float asr[8], ads[8];
#pragma unroll
        for (int i = 0; i < 8; i++) { asr[i] = 0.f; ads[i] = 0.f; }
#pragma unroll
        for (int rp = 0; rp < 4; rp++)
#pragma unroll
            for (int c = 0; c < 4; c++) {
                asr[2*rp]   += A[rp][c].x * asc[c];
                asr[2*rp+1] += A[rp][c].y * asc[c];
                ads[2*rp]   += A[rp][c].x * adc[c];
                ads[2*rp+1] += A[rp][c].y * adc[c];
            }
#pragma unroll
        for (int off = 16; off > 0; off >>= 1)
#pragma unroll
            for (int i = 0; i < 8; i++) {
                asr[i] += __shfl_xor_sync(0xffffffffu, asr[i], off);
                ads[i] += __shfl_xor_sync(0xffffffffu, ads[i], off);
            }
        if (lane == 0) {
#pragma unroll
            for (int i = 0; i < 8; i++) {
                int row = r0 + i;
                if (row < NNODE) {
                    g_asrc[(size_t)b*NNODE + row] = asr[i];
                    g_adst[(size_t)b*NNODE + row] = ads[i];
                }
            }
        }
        // store h as fp16 (halves the edge-gather L2 traffic)
        __half* hb = g_h + (size_t)b*ND;
#pragma unroll
        for (int rp = 0; rp < 4; rp++) {
            int re = r0 + 2*rp, ro = re + 1;
            union { __half2 h[2]; uint2 u; } ce, co;
            ce.h[0] = __floats2half2_rn(A[rp][0].x, A[rp][1].x);
            ce.h[1] = __floats2half2_rn(A[rp][2].x, A[rp][3].x);
            co.h[0] = __floats2half2_rn(A[rp][0].y, A[rp][1].y);
            co.h[1] = __floats2half2_rn(A[rp][2].y, A[rp][3].y);
            if (re < NNODE) *(uint2*)(hb + (size_t)re*DDIM + tx*4) = ce.u;
            if (ro < NNODE) *(uint2*)(hb + (size_t)ro*DDIM + tx*4) = co.u;
        }
    } else {
        float4 b2v = *(const float4*)(b2 + tx*4);
        float4 w3v = *(const float4*)(W3 + DDIM + tx*4);
        float b2c[4] = {b2v.x, b2v.y, b2v.z, b2v.w};
        float w3c[4] = {w3v.x, w3v.y, w3v.z, w3v.w};
        float ra[8];
#pragma unroll
        for (int i = 0; i < 8; i++) ra[i] = 0.f;
#pragma unroll
        for (int rp = 0; rp < 4; rp++)
#pragma unroll
            for (int c = 0; c < 4; c++) {
                float vx = fmaxf(A[rp][c].x + b2c[c], 0.f);
                float vy = fmaxf(A[rp][c].y + b2c[c], 0.f);
                ra[2*rp]   += vx * w3c[c];
                ra[2*rp+1] += vy * w3c[c];
            }
#pragma unroll
        for (int off = 16; off > 0; off >>= 1)
#pragma unroll
            for (int i = 0; i < 8; i++)
                ra[i] += __shfl_xor_sync(0xffffffffu, ra[i], off);
        if (lane == 0) {
            float rsb = g_rs[b];
#pragma unroll
            for (int i = 0; i < 8; i++) {
                int row = r0 + i;
                if (row < NNODE) out[(size_t)b*NNODE + row] = rsb + ra[i];
            }
        }
    }
}

// ---------------- edge softmax + aggregate (one warp per (dst,b)) ----------------
// Pass 1: lane-parallel max over scalar attention logits (4B/edge).
// Pass 2: chain-free exp + fp16 row gather (256B/edge), depth-2 pipelined.
__global__ void k_edge(const float* __restrict__ bias) {
    int gw = (blockIdx.x*blockDim.x + threadIdx.x) >> 5;
    int lane = threadIdx.x & 31;
    if (gw >= NNODE*BNUM) return;
    int n = gw % NNODE;
    int b = gw / NNODE;
    int e0 = g_offs[n], e1 = g_offs[n+1];
    float adst = g_adst[(size_t)b*NNODE + n];
    const float* asr = g_asrc + (size_t)b*NNODE;
    const __half* hb = g_h + (size_t)b*ND;

    // pass 1: max (lane-parallel over edges)
    float mx = -1e30f;
    for (int e = e0 + lane; e < e1; e += 32) {
        float ae = __ldg(&asr[__ldg(&g_srcs[e])]) + adst;
        ae = ae > 0.f ? ae : SLOPE*ae;
        mx = fmaxf(mx, ae);
    }
#pragma unroll
    for (int off = 16; off > 0; off >>= 1)
        mx = fmaxf(mx, __shfl_xor_sync(0xffffffffu, mx, off));

    // pass 2: weighted aggregate, software-pipelined (depth 2)
    float4 acc = {0.f, 0.f, 0.f, 0.f};
    float s = 0.f;
    int sv0 = __ldg(&g_srcs[e0]);
    float a0 = __ldg(&asr[sv0]);
    union { uint2 u; __half2 h[2]; } r0c;
    r0c.u = *(const uint2*)(hb + (size_t)sv0*DDIM + lane*4);
    for (int e = e0; e < e1; ++e) {
        int sv1 = sv0; float a1 = a0;
        union { uint2 u; __half2 h[2]; } r1c; r1c.u = r0c.u;
        if (e + 1 < e1) {
            sv0 = __ldg(&g_srcs[e+1]);
            a0  = __ldg(&asr[sv0]);
            r0c.u = *(const uint2*)(hb + (size_t)sv0*DDIM + lane*4);
        }
        float ae = a1 + adst;
        ae = ae > 0.f ? ae : SLOPE*ae;
        float p = __expf(ae - mx);
        s += p;
        float2 f0 = __half22float2(r1c.h[0]);
        float2 f1 = __half22float2(r1c.h[1]);
        acc.x += p*f0.x;
        acc.y += p*f0.y;
        acc.z += p*f1.x;
        acc.w += p*f1.y;
        (void)sv1;
    }
    float inv = 1.f/s;
    float4 bi = ((const float4*)bias)[lane];
    float4 o;
    o.x = fmaxf(acc.x*inv + bi.x, 0.f);
    o.y = fmaxf(acc.y*inv + bi.y, 0.f);
    o.z = fmaxf(acc.z*inv + bi.z, 0.f);
    o.w = fmaxf(acc.w*inv + bi.w, 0.f);
    ((float4*)(g_x + (size_t)b*ND))[(size_t)n*32 + lane] = o;
}

// ---------------- final head ----------------
__global__ void k_reduce() {
    int b = blockIdx.y;
    int r0 = blockIdx.x * 250;
    int r1 = r0 + 250; if (r1 > NNODE) r1 = NNODE;
    int col = threadIdx.x & 127;
    int half = threadIdx.x >> 7;
    float acc = 0.f;
    const float* xb = g_x + (size_t)b*ND;
    for (int r = r0 + half; r < r1; r += 2) acc += xb[(size_t)r*DDIM + col];
    __shared__ float sh[256];
    sh[threadIdx.x] = acc; __syncthreads();
    if (half == 0)
        g_sembp[((size_t)blockIdx.x*BNUM + b)*DDIM + col] = sh[col] + sh[col+128];
}

__global__ void k_beta(const float* __restrict__ W1, const float* __restrict__ b1,
                       const float* __restrict__ W3, const float* __restrict__ b3) {
    int b = blockIdx.x, d = threadIdx.x;
    __shared__ float semb[DDIM];
    float a = 0.f;
    for (int p = 0; p < RPARTS; p++) a += g_sembp[((size_t)p*BNUM + b)*DDIM + d];
    semb[d] = a; __syncthreads();
    float acc = b1[d];
    for (int k = 0; k < DDIM; k++) acc += semb[k] * W1[k*DDIM + d];
    float v = fmaxf(acc, 0.f) * W3[d];
    __shared__ float sh[DDIM];
    sh[d] = v; __syncthreads();
    for (int off = 64; off > 0; off >>= 1) {
        if (d < off) sh[d] += sh[d+off];
        __syncthreads();
    }
    if (d == 0) g_rs[b] = sh[0] + b3[0];
}

// ---------------- launch ----------------
extern "C" void kernel_launch(void* const* d_in, const int* in_sizes, int n_in,
                              void* d_out, int out_size) {
    const float* state = (const float*)d_in[0];
    const float* struc = (const float*)d_in[1];
    const int*   ei    = (const int*)d_in[2];
    const float* gatW  = (const float*)d_in[3];
    const float* attS  = (const float*)d_in[4];
    const float* attD  = (const float*)d_in[5];
    const float* Wns   = (const float*)d_in[6];
    const float* bns   = (const float*)d_in[7];
    const float* bias  = (const float*)d_in[8];
    const float* W1    = (const float*)d_in[9];
    const float* b1    = (const float*)d_in[10];
    const float* W2    = (const float*)d_in[11];
    const float* b2    = (const float*)d_in[12];
    const float* W3    = (const float*)d_in[13];
    const float* b3    = (const float*)d_in[14];
    float* out = (float*)d_out;
    int Etot = in_sizes[2] / 2;

    // init (count-zero + WnsW precompute fused) + CSR build
    k_init<<<3 + (NNODE+255)/256, 256>>>(gatW, Wns, bns);
    k_hist<<<(Etot+255)/256, 256>>>(ei, Etot);
    k_scan<<<1, 1024>>>(Etot);
    k_scatter<<<(Etot+255)/256, 256>>>(ei, Etot);

    dim3 ggrid((NNODE + 63)/64, BNUM);
    for (int l = 0; l < 3; l++) {
        const float* xe = (l == 0) ? struc : nullptr;
        long bs = (l == 0) ? 0L : (long)ND;
        k_gemm<0><<<ggrid, 256>>>(xe, bs, gatW + (size_t)l*DDIM*DDIM, state,
                                  attS + l*DDIM, attD + l*DDIM, l,
                                  nullptr, nullptr, nullptr);
        k_edge<<<(NNODE*BNUM*32)/256, 256>>>(bias + l*DDIM);
    }

    k_reduce<<<dim3(RPARTS, BNUM), 256>>>();
    k_beta<<<BNUM, 128>>>(W1, b1, W3, b3);
    k_gemm<1><<<ggrid, 256>>>(nullptr, (long)ND, W2, state,
                              nullptr, nullptr, 0, b2, W3, out);
}

// round 5
// speedup vs baseline: 1.3171x; 1.2111x over previous
#include <cuda_runtime.h>
#include <cuda_fp16.h>
#include <cstdint>

#define NNODE 10000
#define BNUM  4
#define DDIM  128
#define ECAP  262144
#define ND    (NNODE*DDIM)
#define SLOPE 0.01f
#define RPARTS 40

// ---------------- scratch (device globals; no allocation) ----------------
__device__ __align__(16) __half g_xh[BNUM*ND];   // layer activations (fp16)
__device__ __align__(16) __half g_strh[ND];      // strucEmb fp16
__device__ __align__(16) __half g_Wh[4*DDIM*DDIM]; // gatW[0..2], W2 as fp16
__device__ __align__(16) __half g_h[BNUM*ND];    // per-layer hidden h (fp16)
__device__ float g_asrc[BNUM*NNODE];
__device__ float g_adst[BNUM*NNODE];
__device__ int   g_offs[NNODE+1];
__device__ int   g_cur[NNODE];
__device__ int   g_srcs[ECAP];
__device__ float g_wnsW[3*DDIM];
__device__ float g_bnsW[3*DDIM];
__device__ float g_sembp[RPARTS*BNUM*DDIM];
__device__ float g_rs[BNUM];

// ---------------- mma helpers ----------------
__device__ __forceinline__ uint32_t su(const void* p) {
    return (uint32_t)__cvta_generic_to_shared(p);
}
__device__ __forceinline__ void ldsm4(uint32_t& r0, uint32_t& r1, uint32_t& r2,
                                      uint32_t& r3, uint32_t addr) {
    asm volatile("ldmatrix.sync.aligned.m8n8.x4.shared.b16 {%0,%1,%2,%3}, [%4];"
                 : "=r"(r0), "=r"(r1), "=r"(r2), "=r"(r3) : "r"(addr));
}
__device__ __forceinline__ void ldsm4t(uint32_t& r0, uint32_t& r1, uint32_t& r2,
                                       uint32_t& r3, uint32_t addr) {
    asm volatile("ldmatrix.sync.aligned.m8n8.x4.trans.shared.b16 {%0,%1,%2,%3}, [%4];"
                 : "=r"(r0), "=r"(r1), "=r"(r2), "=r"(r3) : "r"(addr));
}
__device__ __forceinline__ void mma16816(float* c, uint32_t a0, uint32_t a1,
                                         uint32_t a2, uint32_t a3,
                                         uint32_t b0, uint32_t b1) {
    asm volatile(
        "mma.sync.aligned.m16n8k16.row.col.f32.f16.f16.f32 "
        "{%0,%1,%2,%3}, {%4,%5,%6,%7}, {%8,%9}, {%0,%1,%2,%3};"
        : "+f"(c[0]), "+f"(c[1]), "+f"(c[2]), "+f"(c[3])
        : "r"(a0), "r"(a1), "r"(a2), "r"(a3), "r"(b0), "r"(b1));
}

// ---------------- init: prep + zero + fp16 conversions ----------------
__global__ void k_init(const float* __restrict__ W, const float* __restrict__ W2,
                       const float* __restrict__ Wns, const float* __restrict__ bns,
                       const float* __restrict__ struc) {
    int bb = blockIdx.x;
    if (bb < 3) {
        int l = bb, c = threadIdx.x;
        if (c < DDIM) {
            const float* Wl = W + l*DDIM*DDIM;
            float aw = 0.f, ab = 0.f;
            for (int k = 0; k < DDIM; k++) {
                float w = Wl[k*DDIM + c];
                aw += Wns[l*DDIM + k]*w;
                ab += bns[l*DDIM + k]*w;
            }
            g_wnsW[l*DDIM + c] = aw;
            g_bnsW[l*DDIM + c] = ab;
        }
    } else if (bb < 43) {
        int i = (bb - 3)*256 + threadIdx.x;
        if (i < NNODE) g_cur[i] = 0;
    } else if (bb < 107) {
        // convert 4 weight matrices to fp16 (65536 elems)
        int i0 = (bb - 43)*1024 + threadIdx.x*4;
        int m = i0 >> 14, off = i0 & 16383;
        const float* src = (m < 3) ? (W + m*16384 + off) : (W2 + off);
        float4 v = *(const float4*)src;
        union { __half2 h[2]; uint2 u; } cv;
        cv.h[0] = __floats2half2_rn(v.x, v.y);
        cv.h[1] = __floats2half2_rn(v.z, v.w);
        *(uint2*)&g_Wh[i0] = cv.u;
    } else {
        // convert strucEmb to fp16 (ND = 1,280,000 elems; 1250 blocks)
        int i0 = (bb - 107)*1024 + threadIdx.x*4;
        if (i0 < ND) {
            float4 v = *(const float4*)(struc + i0);
            union { __half2 h[2]; uint2 u; } cv;
            cv.h[0] = __floats2half2_rn(v.x, v.y);
            cv.h[1] = __floats2half2_rn(v.z, v.w);
            *(uint2*)&g_strh[i0] = cv.u;
        }
    }
}

// ---------------- CSR build ----------------
__global__ void k_hist(const int* __restrict__ ei, int Etot) {
    int e = blockIdx.x*blockDim.x + threadIdx.x;
    if (e < Etot) atomicAdd(&g_cur[ei[Etot + e]], 1);
}
__global__ void k_scan(int Etot) {
    __shared__ int sh[1024];
    const int ITEMS = 10;
    int t = threadIdx.x;
    int base = t*ITEMS;
    int loc[ITEMS]; int sum = 0;
#pragma unroll
    for (int i = 0; i < ITEMS; i++) {
        int idx = base + i;
        int v = (idx < NNODE) ? g_cur[idx] : 0;
        loc[i] = sum; sum += v;
    }
    sh[t] = sum; __syncthreads();
    for (int off = 1; off < 1024; off <<= 1) {
        int v = (t >= off) ? sh[t-off] : 0;
        __syncthreads();
        sh[t] += v;
        __syncthreads();
    }
    int pre = t ? sh[t-1] : 0;
#pragma unroll
    for (int i = 0; i < ITEMS; i++) {
        int idx = base + i;
        if (idx < NNODE) { int o = pre + loc[i]; g_offs[idx] = o; g_cur[idx] = o; }
    }
    if (t == 1023) g_offs[NNODE] = sh[1023];
}
__global__ void k_scatter(const int* __restrict__ ei, int Etot) {
    int e = blockIdx.x*blockDim.x + threadIdx.x;
    if (e < Etot) {
        int d = ei[Etot + e];
        int pos = atomicAdd(&g_cur[d], 1);
        g_srcs[pos] = ei[e];
    }
}

// ---------------- HMMA GEMM (64x128 tile, fp16 in / fp32 acc) ----------------
// MODE 0: h = x@W (+ state*WnsW + bnsW) -> g_h fp16, + a_src/a_dst epilogue
// MODE 1: out[b,n] = rs[b] + sum_d relu((x@W2)[d]+b2[d])*W3[128+d]
#define AS_STR 72
#define BS_STR 136
template<int MODE>
__global__ void __launch_bounds__(256)
k_gemm(int widx, const float* __restrict__ state,
       const float* __restrict__ attS, const float* __restrict__ attD,
       const float* __restrict__ b2, const float* __restrict__ W3,
       float* __restrict__ out) {
    __shared__ __align__(16) unsigned char smraw[35840];
    __half* As = (__half*)smraw;                    // [64][72]
    __half* Bs = (__half*)(smraw + 9216);           // [64][136]
    float*  acc_s = (float*)smraw;                  // [64][132] (reused)
    float*  pb = (float*)(smraw + 33792);           // 512 floats of params

    const int tid = threadIdx.x;
    const int lane = tid & 31, warp = tid >> 5;
    const int warpM = warp & 3, warpN = warp >> 2;
    const int b = blockIdx.y;
    const int rowbase = blockIdx.x * 64;

    const __half* xa = (widx == 0) ? g_strh : g_xh;
    const size_t xboff = (widx == 0) ? 0 : (size_t)b * (size_t)ND;
    const __half* Wh = g_Wh + (size_t)widx * DDIM * DDIM;

    // stage per-column params
    for (int i = tid; i < 512; i += 256) {
        int a = i >> 7, c = i & 127;
        float v;
        if (MODE == 0)
            v = (a == 0) ? g_wnsW[widx*DDIM + c] :
                (a == 1) ? g_bnsW[widx*DDIM + c] :
                (a == 2) ? attS[c] : attD[c];
        else
            v = (a == 0) ? b2[c] : (a == 1) ? W3[DDIM + c] : 0.f;
        pb[i] = v;
    }

    float acc[8][4];
#pragma unroll
    for (int i = 0; i < 8; i++)
#pragma unroll
        for (int j = 0; j < 4; j++) acc[i][j] = 0.f;

    const uint32_t asb = su(As), bsb = su(Bs);

#pragma unroll
    for (int kc = 0; kc < 2; ++kc) {
        // stage A: 64 rows x 64 k halves
#pragma unroll
        for (int c = tid; c < 512; c += 256) {
            int r = c >> 3, q = c & 7;
            int rowg = rowbase + r; rowg = rowg < NNODE ? rowg : NNODE-1;
            uint4 v = *(const uint4*)(xa + xboff + (size_t)rowg*DDIM + kc*64 + q*8);
            *(uint4*)&As[r*AS_STR + q*8] = v;
        }
        // stage B: 64 k rows x 128 n halves
#pragma unroll
        for (int c = tid; c < 1024; c += 256) {
            int r = c >> 4, q = c & 15;
            *(uint4*)&Bs[r*BS_STR + q*8] = *(const uint4*)(Wh + (size_t)(kc*64 + r)*DDIM + q*8);
        }
        __syncthreads();
#pragma unroll
        for (int ks = 0; ks < 4; ++ks) {
            uint32_t a0, a1, a2, a3;
            uint32_t aaddr = asb + ((warpM*16 + (lane & 15))*AS_STR
                                    + ks*16 + ((lane >> 4) << 3)) * 2;
            ldsm4(a0, a1, a2, a3, aaddr);
#pragma unroll
            for (int nt = 0; nt < 4; ++nt) {
                uint32_t b0, b1, b2r, b3;
                uint32_t baddr = bsb + ((ks*16 + (lane & 15))*BS_STR
                                        + warpN*64 + nt*16 + ((lane >> 4) << 3)) * 2;
                ldsm4t(b0, b1, b2r, b3, baddr);
                mma16816(acc[nt*2],   a0, a1, a2, a3, b0, b1);
                mma16816(acc[nt*2+1], a0, a1, a2, a3, b2r, b3);
            }
        }
        __syncthreads();
    }

    // spill accumulators to smem for a clean epilogue layout
    {
        int gr = warpM*16 + (lane >> 2);
        int cb0 = warpN*64 + (lane & 3)*2;
#pragma unroll
        for (int nt8 = 0; nt8 < 8; ++nt8) {
            int cb = cb0 + nt8*8;
            acc_s[gr*132 + cb]       = acc[nt8][0];
            acc_s[gr*132 + cb + 1]   = acc[nt8][1];
            acc_s[(gr+8)*132 + cb]   = acc[nt8][2];
            acc_s[(gr+8)*132 + cb+1] = acc[nt8][3];
        }
    }
    __syncthreads();

    const int r = tid >> 2, seg = tid & 3;
    const int row_g = rowbase + r;
    const int rc = row_g < NNODE ? row_g : NNODE-1;

    if (MODE == 0) {
        float st = state[(size_t)b*NNODE + rc];
        float asr = 0.f, ads = 0.f;
        uint32_t hw[16];
#pragma unroll
        for (int i2 = 0; i2 < 16; i2++) {
            int c = seg*32 + i2*2;
            float v0 = acc_s[r*132 + c]     + st*pb[c]     + pb[128 + c];
            float v1 = acc_s[r*132 + c + 1] + st*pb[c + 1] + pb[129 + c];
            asr += v0*pb[256 + c] + v1*pb[257 + c];
            ads += v0*pb[384 + c] + v1*pb[385 + c];
            __half2 h = __floats2half2_rn(v0, v1);
            hw[i2] = *(uint32_t*)&h;
        }
        asr += __shfl_xor_sync(0xffffffffu, asr, 1);
        asr += __shfl_xor_sync(0xffffffffu, asr, 2);
        ads += __shfl_xor_sync(0xffffffffu, ads, 1);
        ads += __shfl_xor_sync(0xffffffffu, ads, 2);
        if (row_g < NNODE) {
            if (seg == 0) {
                g_asrc[(size_t)b*NNODE + row_g] = asr;
                g_adst[(size_t)b*NNODE + row_g] = ads;
            }
            uint4* dst = (uint4*)(g_h + (size_t)b*ND + (size_t)row_g*DDIM + seg*32);
            const uint4* s4 = (const uint4*)hw;
            dst[0] = s4[0]; dst[1] = s4[1]; dst[2] = s4[2]; dst[3] = s4[3];
        }
    } else {
        float ra = 0.f;
#pragma unroll
        for (int i = 0; i < 32; i++) {
            int c = seg*32 + i;
            float v = fmaxf(acc_s[r*132 + c] + pb[c], 0.f);
            ra += v * pb[128 + c];
        }
        ra += __shfl_xor_sync(0xffffffffu, ra, 1);
        ra += __shfl_xor_sync(0xffffffffu, ra, 2);
        if (seg == 0 && row_g < NNODE)
            out[(size_t)b*NNODE + row_g] = g_rs[b] + ra;
    }
}

// ---------------- edge softmax + aggregate (one warp per (dst,b)) ----------------
__global__ void k_edge(const float* __restrict__ bias) {
    int gw = (blockIdx.x*blockDim.x + threadIdx.x) >> 5;
    int lane = threadIdx.x & 31;
    if (gw >= NNODE*BNUM) return;
    int n = gw % NNODE;
    int b = gw / NNODE;
    int e0 = g_offs[n], e1 = g_offs[n+1];
    float adst = g_adst[(size_t)b*NNODE + n];
    const float* asr = g_asrc + (size_t)b*NNODE;
    const __half* hb = g_h + (size_t)b*ND;

    // pass 1: lane-parallel max
    float mx = -1e30f;
    for (int e = e0 + lane; e < e1; e += 32) {
        float ae = __ldg(&asr[__ldg(&g_srcs[e])]) + adst;
        ae = ae > 0.f ? ae : SLOPE*ae;
        mx = fmaxf(mx, ae);
    }
#pragma unroll
    for (int off = 16; off > 0; off >>= 1)
        mx = fmaxf(mx, __shfl_xor_sync(0xffffffffu, mx, off));

    // pass 2: chain-free aggregate, depth-2 pipelined
    float4 acc = {0.f, 0.f, 0.f, 0.f};
    float s = 0.f;
    int sv0 = __ldg(&g_srcs[e0]);
    float a0 = __ldg(&asr[sv0]);
    union { uint2 u; __half2 h[2]; } r0c;
    r0c.u = *(const uint2*)(hb + (size_t)sv0*DDIM + lane*4);
    for (int e = e0; e < e1; ++e) {
        float a1 = a0;
        union { uint2 u; __half2 h[2]; } r1c; r1c.u = r0c.u;
        if (e + 1 < e1) {
            sv0 = __ldg(&g_srcs[e+1]);
            a0  = __ldg(&asr[sv0]);
            r0c.u = *(const uint2*)(hb + (size_t)sv0*DDIM + lane*4);
        }
        float ae = a1 + adst;
        ae = ae > 0.f ? ae : SLOPE*ae;
        float p = __expf(ae - mx);
        s += p;
        float2 f0 = __half22float2(r1c.h[0]);
        float2 f1 = __half22float2(r1c.h[1]);
        acc.x += p*f0.x;
        acc.y += p*f0.y;
        acc.z += p*f1.x;
        acc.w += p*f1.y;
    }
    float inv = 1.f/s;
    float4 bi = ((const float4*)bias)[lane];
    union { uint2 u; __half2 h[2]; } ov;
    ov.h[0] = __floats2half2_rn(fmaxf(acc.x*inv + bi.x, 0.f),
                                fmaxf(acc.y*inv + bi.y, 0.f));
    ov.h[1] = __floats2half2_rn(fmaxf(acc.z*inv + bi.z, 0.f),
                                fmaxf(acc.w*inv + bi.w, 0.f));
    *(uint2*)(g_xh + (size_t)b*ND + (size_t)n*DDIM + lane*4) = ov.u;
}

// ---------------- final head ----------------
__global__ void k_reduce() {
    int b = blockIdx.y;
    int r0 = blockIdx.x * 250;
    int r1 = r0 + 250; if (r1 > NNODE) r1 = NNODE;
    int tid = threadIdx.x;
    int c2 = tid & 63;
    int grp = tid >> 6;
    const __half2* xb = (const __half2*)(g_xh + (size_t)b*ND);
    float ax = 0.f, ay = 0.f;
    for (int r = r0 + grp; r < r1; r += 4) {
        float2 f = __half22float2(xb[(size_t)r*64 + c2]);
        ax += f.x; ay += f.y;
    }
    __shared__ float sx[256], sy[256];
    sx[tid] = ax; sy[tid] = ay; __syncthreads();
    if (grp == 0) {
        float fx = sx[c2] + sx[c2+64] + sx[c2+128] + sx[c2+192];
        float fy = sy[c2] + sy[c2+64] + sy[c2+128] + sy[c2+192];
        float* dst = g_sembp + ((size_t)blockIdx.x*BNUM + b)*DDIM;
        dst[c2*2]   = fx;
        dst[c2*2+1] = fy;
    }
}

__global__ void k_beta(const float* __restrict__ W1, const float* __restrict__ b1,
                       const float* __restrict__ W3, const float* __restrict__ b3) {
    int b = blockIdx.x, d = threadIdx.x;
    __shared__ float semb[DDIM];
    float a = 0.f;
    for (int p = 0; p < RPARTS; p++) a += g_sembp[((size_t)p*BNUM + b)*DDIM + d];
    semb[d] = a; __syncthreads();
    float acc = b1[d];
    for (int k = 0; k < DDIM; k++) acc += semb[k] * W1[k*DDIM + d];
    float v = fmaxf(acc, 0.f) * W3[d];
    __shared__ float sh[DDIM];
    sh[d] = v; __syncthreads();
    for (int off = 64; off > 0; off >>= 1) {
        if (d < off) sh[d] += sh[d+off];
        __syncthreads();
    }
    if (d == 0) g_rs[b] = sh[0] + b3[0];
}

// ---------------- launch ----------------
extern "C" void kernel_launch(void* const* d_in, const int* in_sizes, int n_in,
                              void* d_out, int out_size) {
    const float* state = (const float*)d_in[0];
    const float* struc = (const float*)d_in[1];
    const int*   ei    = (const int*)d_in[2];
    const float* gatW  = (const float*)d_in[3];
    const float* attS  = (const float*)d_in[4];
    const float* attD  = (const float*)d_in[5];
    const float* Wns   = (const float*)d_in[6];
    const float* bns   = (const float*)d_in[7];
    const float* bias  = (const float*)d_in[8];
    const float* W1    = (const float*)d_in[9];
    const float* b1    = (const float*)d_in[10];
    const float* W2    = (const float*)d_in[11];
    const float* b2    = (const float*)d_in[12];
    const float* W3    = (const float*)d_in[13];
    const float* b3    = (const float*)d_in[14];
    float* out = (float*)d_out;
    int Etot = in_sizes[2] / 2;

    k_init<<<107 + ND/1024, 256>>>(gatW, W2, Wns, bns, struc);
    k_hist<<<(Etot+255)/256, 256>>>(ei, Etot);
    k_scan<<<1, 1024>>>(Etot);
    k_scatter<<<(Etot+255)/256, 256>>>(ei, Etot);

    dim3 ggrid((NNODE + 63)/64, BNUM);
    for (int l = 0; l < 3; l++) {
        k_gemm<0><<<ggrid, 256>>>(l, state, attS + l*DDIM, attD + l*DDIM,
                                  nullptr, nullptr, nullptr);
        k_edge<<<(NNODE*BNUM*32)/256, 256>>>(bias + l*DDIM);
    }

    k_reduce<<<dim3(RPARTS, BNUM), 256>>>();
    k_beta<<<BNUM, 128>>>(W1, b1, W3, b3);
    k_gemm<1><<<ggrid, 256>>>(3, state, nullptr, nullptr, b2, W3, out);
}

// round 6
// speedup vs baseline: 1.4768x; 1.1213x over previous
#include <cuda_runtime.h>
#include <cuda_fp16.h>
#include <cstdint>

#define NNODE 10000
#define BNUM  4
#define DDIM  128
#define ECAP  262144
#define ND    (NNODE*DDIM)
#define SLOPE 0.01f
#define RPARTS 40

// ---------------- scratch (device globals; no allocation) ----------------
__device__ __align__(16) __half g_xh[BNUM*ND];   // layer activations (fp16)
__device__ __align__(16) __half g_strh[ND];      // strucEmb fp16
__device__ __align__(16) __half g_Wh[4*DDIM*DDIM]; // gatW[0..2], W2 as fp16
__device__ __align__(16) __half g_h[BNUM*ND];    // per-layer hidden h (fp16)
__device__ __align__(16) float g_asrcT[NNODE*4]; // [n][b] transposed logits
__device__ __align__(16) float g_adstT[NNODE*4];
__device__ int   g_offs[NNODE+1];
__device__ int   g_cur[NNODE];
__device__ int   g_srcs[ECAP];
__device__ float g_wnsW[3*DDIM];
__device__ float g_bnsW[3*DDIM];
__device__ float g_sembp[RPARTS*BNUM*DDIM];
__device__ float g_rs[BNUM];

// ---------------- mma helpers ----------------
__device__ __forceinline__ uint32_t su(const void* p) {
    return (uint32_t)__cvta_generic_to_shared(p);
}
__device__ __forceinline__ void ldsm4(uint32_t& r0, uint32_t& r1, uint32_t& r2,
                                      uint32_t& r3, uint32_t addr) {
    asm volatile("ldmatrix.sync.aligned.m8n8.x4.shared.b16 {%0,%1,%2,%3}, [%4];"
                 : "=r"(r0), "=r"(r1), "=r"(r2), "=r"(r3) : "r"(addr));
}
__device__ __forceinline__ void ldsm4t(uint32_t& r0, uint32_t& r1, uint32_t& r2,
                                       uint32_t& r3, uint32_t addr) {
    asm volatile("ldmatrix.sync.aligned.m8n8.x4.trans.shared.b16 {%0,%1,%2,%3}, [%4];"
                 : "=r"(r0), "=r"(r1), "=r"(r2), "=r"(r3) : "r"(addr));
}
__device__ __forceinline__ void mma16816(float* c, uint32_t a0, uint32_t a1,
                                         uint32_t a2, uint32_t a3,
                                         uint32_t b0, uint32_t b1) {
    asm volatile(
        "mma.sync.aligned.m16n8k16.row.col.f32.f16.f16.f32 "
        "{%0,%1,%2,%3}, {%4,%5,%6,%7}, {%8,%9}, {%0,%1,%2,%3};"
        : "+f"(c[0]), "+f"(c[1]), "+f"(c[2]), "+f"(c[3])
        : "r"(a0), "r"(a1), "r"(a2), "r"(a3), "r"(b0), "r"(b1));
}

// ---------------- init: prep + zero + fp16 conversions ----------------
__global__ void k_init(const float* __restrict__ W, const float* __restrict__ W2,
                       const float* __restrict__ Wns, const float* __restrict__ bns,
                       const float* __restrict__ struc) {
    int bb = blockIdx.x;
    if (bb < 3) {
        int l = bb, c = threadIdx.x;
        if (c < DDIM) {
            const float* Wl = W + l*DDIM*DDIM;
            float aw = 0.f, ab = 0.f;
            for (int k = 0; k < DDIM; k++) {
                float w = Wl[k*DDIM + c];
                aw += Wns[l*DDIM + k]*w;
                ab += bns[l*DDIM + k]*w;
            }
            g_wnsW[l*DDIM + c] = aw;
            g_bnsW[l*DDIM + c] = ab;
        }
    } else if (bb < 43) {
        int i = (bb - 3)*256 + threadIdx.x;
        if (i < NNODE) g_cur[i] = 0;
    } else if (bb < 107) {
        int i0 = (bb - 43)*1024 + threadIdx.x*4;
        int m = i0 >> 14, off = i0 & 16383;
        const float* src = (m < 3) ? (W + m*16384 + off) : (W2 + off);
        float4 v = *(const float4*)src;
        union { __half2 h[2]; uint2 u; } cv;
        cv.h[0] = __floats2half2_rn(v.x, v.y);
        cv.h[1] = __floats2half2_rn(v.z, v.w);
        *(uint2*)&g_Wh[i0] = cv.u;
    } else {
        int i0 = (bb - 107)*1024 + threadIdx.x*4;
        if (i0 < ND) {
            float4 v = *(const float4*)(struc + i0);
            union { __half2 h[2]; uint2 u; } cv;
            cv.h[0] = __floats2half2_rn(v.x, v.y);
            cv.h[1] = __floats2half2_rn(v.z, v.w);
            *(uint2*)&g_strh[i0] = cv.u;
        }
    }
}

// ---------------- CSR build ----------------
__global__ void k_hist(const int* __restrict__ ei, int Etot) {
    int e = blockIdx.x*blockDim.x + threadIdx.x;
    if (e < Etot) atomicAdd(&g_cur[ei[Etot + e]], 1);
}
__global__ void k_scan(int Etot) {
    __shared__ int sh[1024];
    const int ITEMS = 10;
    int t = threadIdx.x;
    int base = t*ITEMS;
    int loc[ITEMS]; int sum = 0;
#pragma unroll
    for (int i = 0; i < ITEMS; i++) {
        int idx = base + i;
        int v = (idx < NNODE) ? g_cur[idx] : 0;
        loc[i] = sum; sum += v;
    }
    sh[t] = sum; __syncthreads();
    for (int off = 1; off < 1024; off <<= 1) {
        int v = (t >= off) ? sh[t-off] : 0;
        __syncthreads();
        sh[t] += v;
        __syncthreads();
    }
    int pre = t ? sh[t-1] : 0;
#pragma unroll
    for (int i = 0; i < ITEMS; i++) {
        int idx = base + i;
        if (idx < NNODE) { int o = pre + loc[i]; g_offs[idx] = o; g_cur[idx] = o; }
    }
    if (t == 1023) g_offs[NNODE] = sh[1023];
}
__global__ void k_scatter(const int* __restrict__ ei, int Etot) {
    int e = blockIdx.x*blockDim.x + threadIdx.x;
    if (e < Etot) {
        int d = ei[Etot + e];
        int pos = atomicAdd(&g_cur[d], 1);
        g_srcs[pos] = ei[e];
    }
}

// ---------------- HMMA GEMM (64x128 tile, fp16 in / fp32 acc) ----------------
#define AS_STR 72
#define BS_STR 136
template<int MODE>
__global__ void __launch_bounds__(256)
k_gemm(int widx, const float* __restrict__ state,
       const float* __restrict__ attS, const float* __restrict__ attD,
       const float* __restrict__ b2, const float* __restrict__ W3,
       float* __restrict__ out) {
    __shared__ __align__(16) unsigned char smraw[35840];
    __half* As = (__half*)smraw;                    // [64][72]
    __half* Bs = (__half*)(smraw + 9216);           // [64][136]
    float*  acc_s = (float*)smraw;                  // [64][132] (reused)
    float*  pb = (float*)(smraw + 33792);           // 512 floats of params

    const int tid = threadIdx.x;
    const int lane = tid & 31, warp = tid >> 5;
    const int warpM = warp & 3, warpN = warp >> 2;
    const int b = blockIdx.y;
    const int rowbase = blockIdx.x * 64;

    const __half* xa = (widx == 0) ? g_strh : g_xh;
    const size_t xboff = (widx == 0) ? 0 : (size_t)b * (size_t)ND;
    const __half* Wh = g_Wh + (size_t)widx * DDIM * DDIM;

    for (int i = tid; i < 512; i += 256) {
        int a = i >> 7, c = i & 127;
        float v;
        if (MODE == 0)
            v = (a == 0) ? g_wnsW[widx*DDIM + c] :
                (a == 1) ? g_bnsW[widx*DDIM + c] :
                (a == 2) ? attS[c] : attD[c];
        else
            v = (a == 0) ? b2[c] : (a == 1) ? W3[DDIM + c] : 0.f;
        pb[i] = v;
    }

    float acc[8][4];
#pragma unroll
    for (int i = 0; i < 8; i++)
#pragma unroll
        for (int j = 0; j < 4; j++) acc[i][j] = 0.f;

    const uint32_t asb = su(As), bsb = su(Bs);

#pragma unroll
    for (int kc = 0; kc < 2; ++kc) {
#pragma unroll
        for (int c = tid; c < 512; c += 256) {
            int r = c >> 3, q = c & 7;
            int rowg = rowbase + r; rowg = rowg < NNODE ? rowg : NNODE-1;
            uint4 v = *(const uint4*)(xa + xboff + (size_t)rowg*DDIM + kc*64 + q*8);
            *(uint4*)&As[r*AS_STR + q*8] = v;
        }
#pragma unroll
        for (int c = tid; c < 1024; c += 256) {
            int r = c >> 4, q = c & 15;
            *(uint4*)&Bs[r*BS_STR + q*8] = *(const uint4*)(Wh + (size_t)(kc*64 + r)*DDIM + q*8);
        }
        __syncthreads();
#pragma unroll
        for (int ks = 0; ks < 4; ++ks) {
            uint32_t a0, a1, a2, a3;
            uint32_t aaddr = asb + ((warpM*16 + (lane & 15))*AS_STR
                                    + ks*16 + ((lane >> 4) << 3)) * 2;
            ldsm4(a0, a1, a2, a3, aaddr);
#pragma unroll
            for (int nt = 0; nt < 4; ++nt) {
                uint32_t b0, b1, b2r, b3;
                uint32_t baddr = bsb + ((ks*16 + (lane & 15))*BS_STR
                                        + warpN*64 + nt*16 + ((lane >> 4) << 3)) * 2;
                ldsm4t(b0, b1, b2r, b3, baddr);
                mma16816(acc[nt*2],   a0, a1, a2, a3, b0, b1);
                mma16816(acc[nt*2+1], a0, a1, a2, a3, b2r, b3);
            }
        }
        __syncthreads();
    }

    {
        int gr = warpM*16 + (lane >> 2);
        int cb0 = warpN*64 + (lane & 3)*2;
#pragma unroll
        for (int nt8 = 0; nt8 < 8; ++nt8) {
            int cb = cb0 + nt8*8;
            acc_s[gr*132 + cb]       = acc[nt8][0];
            acc_s[gr*132 + cb + 1]   = acc[nt8][1];
            acc_s[(gr+8)*132 + cb]   = acc[nt8][2];
            acc_s[(gr+8)*132 + cb+1] = acc[nt8][3];
        }
    }
    __syncthreads();

    const int r = tid >> 2, seg = tid & 3;
    const int row_g = rowbase + r;
    const int rc = row_g < NNODE ? row_g : NNODE-1;

    if (MODE == 0) {
        float st = state[(size_t)b*NNODE + rc];
        float asr = 0.f, ads = 0.f;
        uint32_t hw[16];
#pragma unroll
        for (int i2 = 0; i2 < 16; i2++) {
            int c = seg*32 + i2*2;
            float v0 = acc_s[r*132 + c]     + st*pb[c]     + pb[128 + c];
            float v1 = acc_s[r*132 + c + 1] + st*pb[c + 1] + pb[129 + c];
            asr += v0*pb[256 + c] + v1*pb[257 + c];
            ads += v0*pb[384 + c] + v1*pb[385 + c];
            __half2 h = __floats2half2_rn(v0, v1);
            hw[i2] = *(uint32_t*)&h;
        }
        asr += __shfl_xor_sync(0xffffffffu, asr, 1);
        asr += __shfl_xor_sync(0xffffffffu, asr, 2);
        ads += __shfl_xor_sync(0xffffffffu, ads, 1);
        ads += __shfl_xor_sync(0xffffffffu, ads, 2);
        if (row_g < NNODE) {
            if (seg == 0) {
                g_asrcT[row_g*4 + b] = asr;   // transposed: [n][b]
                g_adstT[row_g*4 + b] = ads;
            }
            uint4* dst = (uint4*)(g_h + (size_t)b*ND + (size_t)row_g*DDIM + seg*32);
            const uint4* s4 = (const uint4*)hw;
            dst[0] = s4[0]; dst[1] = s4[1]; dst[2] = s4[2]; dst[3] = s4[3];
        }
    } else {
        float ra = 0.f;
#pragma unroll
        for (int i = 0; i < 32; i++) {
            int c = seg*32 + i;
            float v = fmaxf(acc_s[r*132 + c] + pb[c], 0.f);
            ra += v * pb[128 + c];
        }
        ra += __shfl_xor_sync(0xffffffffu, ra, 1);
        ra += __shfl_xor_sync(0xffffffffu, ra, 2);
        if (seg == 0 && row_g < NNODE)
            out[(size_t)b*NNODE + row_g] = g_rs[b] + ra;
    }
}

// ---------------- edge softmax + aggregate ----------------
// One warp per dst node, ALL 4 batches fused. Single pass, no max
// (logits are O(1): exp(ae)/sum(exp(ae)) is exact-ratio and overflow-safe).
__device__ __forceinline__ void edge_acc(float a, float ad, uint2 hv,
                                         float4& acc, float& s) {
    float ae = a + ad;
    ae = ae > 0.f ? ae : SLOPE*ae;
    float p = __expf(ae);
    s += p;
    union { uint2 u; __half2 h[2]; } c; c.u = hv;
    float2 f0 = __half22float2(c.h[0]);
    float2 f1 = __half22float2(c.h[1]);
    acc.x += p*f0.x; acc.y += p*f0.y;
    acc.z += p*f1.x; acc.w += p*f1.y;
}

__global__ void __launch_bounds__(256) k_edge(const float* __restrict__ bias) {
    int n = (blockIdx.x*blockDim.x + threadIdx.x) >> 5;
    int lane = threadIdx.x & 31;
    if (n >= NNODE) return;
    int e0 = g_offs[n], e1 = g_offs[n+1];
    const float4 ad = *(const float4*)&g_adstT[n*4];

    float4 acc0 = {0,0,0,0}, acc1 = {0,0,0,0}, acc2 = {0,0,0,0}, acc3 = {0,0,0,0};
    float s0 = 0.f, s1 = 0.f, s2 = 0.f, s3 = 0.f;

    // depth-2 pipeline
    int sv = __ldg(&g_srcs[e0]);
    float4 as = *(const float4*)&g_asrcT[sv*4];
    const __half* hr = g_h + (size_t)sv*DDIM + lane*4;
    uint2 h0 = *(const uint2*)(hr);
    uint2 h1 = *(const uint2*)(hr + ND);
    uint2 h2 = *(const uint2*)(hr + 2*(size_t)ND);
    uint2 h3 = *(const uint2*)(hr + 3*(size_t)ND);

    for (int e = e0; e < e1; ++e) {
        float4 asc = as;
        uint2 c0 = h0, c1 = h1, c2 = h2, c3 = h3;
        if (e + 1 < e1) {
            sv = __ldg(&g_srcs[e+1]);
            as = *(const float4*)&g_asrcT[sv*4];
            hr = g_h + (size_t)sv*DDIM + lane*4;
            h0 = *(const uint2*)(hr);
            h1 = *(const uint2*)(hr + ND);
            h2 = *(const uint2*)(hr + 2*(size_t)ND);
            h3 = *(const uint2*)(hr + 3*(size_t)ND);
        }
        edge_acc(asc.x, ad.x, c0, acc0, s0);
        edge_acc(asc.y, ad.y, c1, acc1, s1);
        edge_acc(asc.z, ad.z, c2, acc2, s2);
        edge_acc(asc.w, ad.w, c3, acc3, s3);
    }

    float4 bi = ((const float4*)bias)[lane];
    float4* accs[4] = {&acc0, &acc1, &acc2, &acc3};
    float ss[4] = {s0, s1, s2, s3};
#pragma unroll
    for (int b = 0; b < 4; b++) {
        float inv = 1.f / ss[b];
        float4 a = *accs[b];
        union { uint2 u; __half2 h[2]; } ov;
        ov.h[0] = __floats2half2_rn(fmaxf(a.x*inv + bi.x, 0.f),
                                    fmaxf(a.y*inv + bi.y, 0.f));
        ov.h[1] = __floats2half2_rn(fmaxf(a.z*inv + bi.z, 0.f),
                                    fmaxf(a.w*inv + bi.w, 0.f));
        *(uint2*)(g_xh + (size_t)b*ND + (size_t)n*DDIM + lane*4) = ov.u;
    }
}

// ---------------- final head ----------------
__global__ void k_reduce() {
    int b = blockIdx.y;
    int r0 = blockIdx.x * 250;
    int r1 = r0 + 250; if (r1 > NNODE) r1 = NNODE;
    int tid = threadIdx.x;
    int c2 = tid & 63;
    int grp = tid >> 6;
    const __half2* xb = (const __half2*)(g_xh + (size_t)b*ND);
    float ax = 0.f, ay = 0.f;
    for (int r = r0 + grp; r < r1; r += 4) {
        float2 f = __half22float2(xb[(size_t)r*64 + c2]);
        ax += f.x; ay += f.y;
    }
    __shared__ float sx[256], sy[256];
    sx[tid] = ax; sy[tid] = ay; __syncthreads();
    if (grp == 0) {
        float fx = sx[c2] + sx[c2+64] + sx[c2+128] + sx[c2+192];
        float fy = sy[c2] + sy[c2+64] + sy[c2+128] + sy[c2+192];
        float* dst = g_sembp + ((size_t)blockIdx.x*BNUM + b)*DDIM;
        dst[c2*2]   = fx;
        dst[c2*2+1] = fy;
    }
}

__global__ void k_beta(const float* __restrict__ W1, const float* __restrict__ b1,
                       const float* __restrict__ W3, const float* __restrict__ b3) {
    int b = blockIdx.x, d = threadIdx.x;
    __shared__ float semb[DDIM];
    float a = 0.f;
    for (int p = 0; p < RPARTS; p++) a += g_sembp[((size_t)p*BNUM + b)*DDIM + d];
    semb[d] = a; __syncthreads();
    float acc = b1[d];
    for (int k = 0; k < DDIM; k++) acc += semb[k] * W1[k*DDIM + d];
    float v = fmaxf(acc, 0.f) * W3[d];
    __shared__ float sh[DDIM];
    sh[d] = v; __syncthreads();
    for (int off = 64; off > 0; off >>= 1) {
        if (d < off) sh[d] += sh[d+off];
        __syncthreads();
    }
    if (d == 0) g_rs[b] = sh[0] + b3[0];
}

// ---------------- launch ----------------
extern "C" void kernel_launch(void* const* d_in, const int* in_sizes, int n_in,
                              void* d_out, int out_size) {
    const float* state = (const float*)d_in[0];
    const float* struc = (const float*)d_in[1];
    const int*   ei    = (const int*)d_in[2];
    const float* gatW  = (const float*)d_in[3];
    const float* attS  = (const float*)d_in[4];
    const float* attD  = (const float*)d_in[5];
    const float* Wns   = (const float*)d_in[6];
    const float* bns   = (const float*)d_in[7];
    const float* bias  = (const float*)d_in[8];
    const float* W1    = (const float*)d_in[9];
    const float* b1    = (const float*)d_in[10];
    const float* W2    = (const float*)d_in[11];
    const float* b2    = (const float*)d_in[12];
    const float* W3    = (const float*)d_in[13];
    const float* b3    = (const float*)d_in[14];
    float* out = (float*)d_out;
    int Etot = in_sizes[2] / 2;

    k_init<<<107 + ND/1024, 256>>>(gatW, W2, Wns, bns, struc);
    k_hist<<<(Etot+255)/256, 256>>>(ei, Etot);
    k_scan<<<1, 1024>>>(Etot);
    k_scatter<<<(Etot+255)/256, 256>>>(ei, Etot);

    dim3 ggrid((NNODE + 63)/64, BNUM);
    for (int l = 0; l < 3; l++) {
        k_gemm<0><<<ggrid, 256>>>(l, state, attS + l*DDIM, attD + l*DDIM,
                                  nullptr, nullptr, nullptr);
        k_edge<<<(NNODE*32 + 255)/256, 256>>>(bias + l*DDIM);
    }

    k_reduce<<<dim3(RPARTS, BNUM), 256>>>();
    k_beta<<<BNUM, 128>>>(W1, b1, W3, b3);
    k_gemm<1><<<ggrid, 256>>>(3, state, nullptr, nullptr, b2, W3, out);
}